// round 1
// baseline (speedup 1.0000x reference)
#include <cuda_runtime.h>

#define BB 256
#define NIN 2048
#define NH 2048
#define NC 100
#define TSTEPS 25
#define NSPLIT 16
#define KSPLIT (NH / NSPLIT)   // 128
#define BETA 0.95f
#define THRESH 1.0f

// ---------------- scratch (device globals; no allocations allowed) -----------
__device__ float g_C1[BB * NH];         // loop-invariant layer-1 current
__device__ float g_m1[BB * NH];
__device__ float g_spk1[BB * NH];
__device__ float g_m2[BB * NH];
__device__ float g_spk2[BB * NH];
__device__ float g_m3[BB * NC];
__device__ float g_part[NSPLIT * BB * NC];  // split-K partials for layer 3

// ---------------- zero membrane state ----------------------------------------
__global__ void zero_states_kernel() {
    int i = blockIdx.x * blockDim.x + threadIdx.x;
    if (i < BB * NH) { g_m1[i] = 0.0f; g_m2[i] = 0.0f; }
    if (i < BB * NC) { g_m3[i] = 0.0f; }
}

// ---------------- layer-1 LIF (elementwise, cur1 precomputed) ----------------
__global__ void lif1_kernel() {
    int i = blockIdx.x * blockDim.x + threadIdx.x;  // float4 index, BB*NH/4 total
    float4 c = ((const float4*)g_C1)[i];
    float4 m = ((const float4*)g_m1)[i];
    float4 s;
    m.x = BETA * m.x + c.x; s.x = (m.x > THRESH) ? 1.0f : 0.0f; m.x -= s.x * THRESH;
    m.y = BETA * m.y + c.y; s.y = (m.y > THRESH) ? 1.0f : 0.0f; m.y -= s.y * THRESH;
    m.z = BETA * m.z + c.z; s.z = (m.z > THRESH) ? 1.0f : 0.0f; m.z -= s.z * THRESH;
    m.w = BETA * m.w + c.w; s.w = (m.w > THRESH) ? 1.0f : 0.0f; m.w -= s.w * THRESH;
    ((float4*)g_m1)[i]   = m;
    ((float4*)g_spk1)[i] = s;
}

// ---------------- generic GEMM  C = A[M,K] @ W[N,K]^T + bias -----------------
// mode 0: write C to Cout (used once for cur1)
// mode 1: fused LIF epilogue: mem = beta*mem + C; spk = mem>1; mem -= spk
// tiles: BM=32, BN=128, BK=16; 128 threads; thread tile 4x8
__global__ void __launch_bounds__(128)
gemm_lif_kernel(const float* __restrict__ A, const float* __restrict__ W,
                const float* __restrict__ bias, float* __restrict__ Cout,
                float* __restrict__ mem, float* __restrict__ spk,
                int K, int N, int mode)
{
    __shared__ float As[16][32];
    __shared__ float Bs[16][128];

    const int bm  = blockIdx.x * 32;
    const int bn  = blockIdx.y * 128;
    const int tid = threadIdx.x;
    const int tr  = tid >> 4;         // 0..7   (row group of 4)
    const int tc  = tid & 15;         // 0..15  (col group of 8)
    const int lr  = tid >> 2;         // 0..31  (load row)
    const int lc  = (tid & 3) << 2;   // 0,4,8,12 (load k-offset)

    float acc[4][8];
#pragma unroll
    for (int i = 0; i < 4; i++)
#pragma unroll
        for (int j = 0; j < 8; j++) acc[i][j] = 0.0f;

    const float* Aptr = A + (size_t)(bm + lr) * K + lc;
    const float* Wptr = W + (size_t)(bn + lr) * K + lc;

    for (int k0 = 0; k0 < K; k0 += 16) {
        float4 av = *(const float4*)(Aptr + k0);
        As[lc + 0][lr] = av.x; As[lc + 1][lr] = av.y;
        As[lc + 2][lr] = av.z; As[lc + 3][lr] = av.w;
#pragma unroll
        for (int i = 0; i < 4; i++) {
            float4 wv = *(const float4*)(Wptr + (size_t)i * 32 * K + k0);
            int nr = lr + i * 32;
            Bs[lc + 0][nr] = wv.x; Bs[lc + 1][nr] = wv.y;
            Bs[lc + 2][nr] = wv.z; Bs[lc + 3][nr] = wv.w;
        }
        __syncthreads();
#pragma unroll
        for (int k = 0; k < 16; k++) {
            float a[4], b[8];
            *(float4*)a       = *(const float4*)&As[k][tr * 4];
            *(float4*)b       = *(const float4*)&Bs[k][tc * 8];
            *(float4*)(b + 4) = *(const float4*)&Bs[k][tc * 8 + 4];
#pragma unroll
            for (int i = 0; i < 4; i++)
#pragma unroll
                for (int j = 0; j < 8; j++)
                    acc[i][j] += a[i] * b[j];
        }
        __syncthreads();
    }

#pragma unroll
    for (int i = 0; i < 4; i++) {
        int r = bm + tr * 4 + i;
#pragma unroll
        for (int j = 0; j < 8; j++) {
            int c = bn + tc * 8 + j;
            float cur = acc[i][j] + bias[c];
            size_t idx = (size_t)r * N + c;
            if (mode == 0) {
                Cout[idx] = cur;
            } else {
                float m = BETA * mem[idx] + cur;
                float s = (m > THRESH) ? 1.0f : 0.0f;
                m -= s * THRESH;
                mem[idx] = m;
                spk[idx] = s;
            }
        }
    }
}

// ---------------- layer-3 split-K GEMM (deterministic partials) --------------
// grid (BB/32, NSPLIT), 256 threads. Each block: 32 rows x 100 cols over K=128.
__global__ void __launch_bounds__(256)
gemm3_kernel(const float* __restrict__ Aspk, const float* __restrict__ W3)
{
    __shared__ float Ss[KSPLIT][32];   // [k][m], 16 KB

    const int mtile = blockIdx.x * 32;
    const int ks    = blockIdx.y;
    const int k0    = ks * KSPLIT;
    const int tid   = threadIdx.x;

#pragma unroll
    for (int it = 0; it < 4; it++) {
        int idx = tid + it * 256;       // 0..1023 float4 loads
        int m   = idx >> 5;             // 0..31
        int kq  = (idx & 31) << 2;      // 0..124
        float4 v = *(const float4*)(Aspk + (size_t)(mtile + m) * NH + k0 + kq);
        Ss[kq + 0][m] = v.x; Ss[kq + 1][m] = v.y;
        Ss[kq + 2][m] = v.z; Ss[kq + 3][m] = v.w;
    }
    __syncthreads();

    const int n  = tid % NC;
    const int mg = tid / NC;            // 0 or 1 active, rest idle
    if (mg >= 2) return;

    float acc[16];
#pragma unroll
    for (int i = 0; i < 16; i++) acc[i] = 0.0f;

    const float* wrow = W3 + (size_t)n * NH + k0;
    for (int kk = 0; kk < KSPLIT; kk += 4) {
        float4 w4 = *(const float4*)(wrow + kk);
        float wv[4] = {w4.x, w4.y, w4.z, w4.w};
#pragma unroll
        for (int q = 0; q < 4; q++) {
            int k = kk + q;
            float4 s0 = *(const float4*)&Ss[k][mg * 16 + 0];
            float4 s1 = *(const float4*)&Ss[k][mg * 16 + 4];
            float4 s2 = *(const float4*)&Ss[k][mg * 16 + 8];
            float4 s3 = *(const float4*)&Ss[k][mg * 16 + 12];
            float w = wv[q];
            acc[0]  += w * s0.x; acc[1]  += w * s0.y; acc[2]  += w * s0.z; acc[3]  += w * s0.w;
            acc[4]  += w * s1.x; acc[5]  += w * s1.y; acc[6]  += w * s1.z; acc[7]  += w * s1.w;
            acc[8]  += w * s2.x; acc[9]  += w * s2.y; acc[10] += w * s2.z; acc[11] += w * s2.w;
            acc[12] += w * s3.x; acc[13] += w * s3.y; acc[14] += w * s3.z; acc[15] += w * s3.w;
        }
    }
#pragma unroll
    for (int i = 0; i < 16; i++)
        g_part[(size_t)ks * (BB * NC) + (size_t)(mtile + mg * 16 + i) * NC + n] = acc[i];
}

// ---------------- layer-3 LIF + split-K reduce + output write ----------------
__global__ void lif3_kernel(const float* __restrict__ b3, float* __restrict__ out, int t)
{
    int i = blockIdx.x * blockDim.x + threadIdx.x;   // 0 .. BB*NC-1
    if (i >= BB * NC) return;
    int n = i % NC;
    float cur = b3[n];
#pragma unroll
    for (int s = 0; s < NSPLIT; s++) cur += g_part[s * (BB * NC) + i];
    float m  = BETA * g_m3[i] + cur;
    float sp = (m > THRESH) ? 1.0f : 0.0f;
    m -= sp * THRESH;
    g_m3[i] = m;
    out[(size_t)t * (BB * NC) + i]                          = sp;  // spk_rec
    out[(size_t)TSTEPS * (BB * NC) + (size_t)t * (BB * NC) + i] = m;   // mem_rec
}

// ---------------- launch ------------------------------------------------------
extern "C" void kernel_launch(void* const* d_in, const int* in_sizes, int n_in,
                              void* d_out, int out_size)
{
    const float* x  = (const float*)d_in[0];
    const float* W1 = (const float*)d_in[1];
    const float* b1 = (const float*)d_in[2];
    const float* W2 = (const float*)d_in[3];
    const float* b2 = (const float*)d_in[4];
    const float* W3 = (const float*)d_in[5];
    const float* b3 = (const float*)d_in[6];
    float* out = (float*)d_out;

    float *pC1, *pm2, *pspk1, *pspk2;
    cudaGetSymbolAddress((void**)&pC1,   g_C1);
    cudaGetSymbolAddress((void**)&pm2,   g_m2);
    cudaGetSymbolAddress((void**)&pspk1, g_spk1);
    cudaGetSymbolAddress((void**)&pspk2, g_spk2);

    // reset state every call (deterministic)
    zero_states_kernel<<<(BB * NH + 255) / 256, 256>>>();

    // loop-invariant: cur1 = x @ W1^T + b1 (computed once)
    gemm_lif_kernel<<<dim3(BB / 32, NH / 128), 128>>>(
        x, W1, b1, pC1, nullptr, nullptr, NIN, NH, 0);

    for (int t = 0; t < TSTEPS; t++) {
        lif1_kernel<<<(BB * NH / 4) / 256, 256>>>();
        gemm_lif_kernel<<<dim3(BB / 32, NH / 128), 128>>>(
            pspk1, W2, b2, nullptr, pm2, pspk2, NH, NH, 1);
        gemm3_kernel<<<dim3(BB / 32, NSPLIT), 256>>>(pspk2, W3);
        lif3_kernel<<<(BB * NC + 255) / 256, 256>>>(b3, out, t);
    }
}

// round 3
// speedup vs baseline: 3.7742x; 3.7742x over previous
#include <cuda_runtime.h>
#include <cuda_bf16.h>
#include <cstdint>

#define BB 256
#define NIN 2048
#define NH 2048
#define NC 100
#define NCP 128
#define TSTEPS 25
#define MT (TSTEPS*BB)   // 6400
#define BETA 0.95f
#define THRESH 1.0f

typedef __nv_bfloat16 bf16;

// ---------------- scratch (device globals; no allocations allowed) -----------
__device__ __align__(256) bf16 g_w2h[NH*NH],  g_w2m[NH*NH],  g_w2l[NH*NH];
__device__ __align__(256) bf16 g_w3h[NCP*NH], g_w3m[NCP*NH], g_w3l[NCP*NH];
__device__ __align__(256) float g_b3p[NCP];
__device__ __align__(256) float g_C1[BB*NH];        // cur1 (+b1), loop-invariant
__device__ __align__(256) bf16  g_spk1[MT*NH];      // [t][b][n]
__device__ __align__(256) float g_C2[MT*NH];        // cur2 (+b2) for all steps
__device__ __align__(256) bf16  g_spk2[MT*NH];
__device__ __align__(256) float g_C3[MT*NCP];       // cur3 (+b3) for all steps

// ---------------- 3-way bf16 split: v = h + m + l (exact to ~24 bits) --------
__global__ void conv3_kernel(const float* __restrict__ src,
                             bf16* __restrict__ h, bf16* __restrict__ m,
                             bf16* __restrict__ l, int n)
{
    int i = blockIdx.x * blockDim.x + threadIdx.x;
    if (i >= n) return;
    float v  = src[i];
    bf16 hv  = __float2bfloat16_rn(v);
    float r1 = v - __bfloat162float(hv);
    bf16 mv  = __float2bfloat16_rn(r1);
    float r2 = r1 - __bfloat162float(mv);
    h[i] = hv; m[i] = mv; l[i] = __float2bfloat16_rn(r2);
}

// W3 padded to 128 rows (rows >= 100 are zero)
__global__ void conv3_w3_kernel(const float* __restrict__ W3)
{
    int i = blockIdx.x * blockDim.x + threadIdx.x;   // 0 .. NCP*NH-1
    if (i >= NCP * NH) return;
    int row = i >> 11;
    float v = (row < NC) ? W3[(size_t)row * NH + (i & (NH - 1))] : 0.0f;
    bf16 hv  = __float2bfloat16_rn(v);
    float r1 = v - __bfloat162float(hv);
    bf16 mv  = __float2bfloat16_rn(r1);
    float r2 = r1 - __bfloat162float(mv);
    g_w3h[i] = hv; g_w3m[i] = mv; g_w3l[i] = __float2bfloat16_rn(r2);
}

__global__ void b3pad_kernel(const float* __restrict__ b3)
{
    int i = threadIdx.x;
    if (i < NCP) g_b3p[i] = (i < NC) ? b3[i] : 0.0f;
}

// ---------------- fp32 SIMT GEMM (proven round-1 kernel, mode-0 path) --------
// C = A[M,K] @ W[N,K]^T + bias. BM=32, BN=128, BK=16; 128 threads.
__global__ void __launch_bounds__(128)
gemm_f32_kernel(const float* __restrict__ A, const float* __restrict__ W,
                const float* __restrict__ bias, float* __restrict__ Cout,
                int K, int N)
{
    __shared__ float As[16][32];
    __shared__ float Bs[16][128];

    const int bm  = blockIdx.x * 32;
    const int bn  = blockIdx.y * 128;
    const int tid = threadIdx.x;
    const int tr  = tid >> 4;
    const int tc  = tid & 15;
    const int lr  = tid >> 2;
    const int lc  = (tid & 3) << 2;

    float acc[4][8];
#pragma unroll
    for (int i = 0; i < 4; i++)
#pragma unroll
        for (int j = 0; j < 8; j++) acc[i][j] = 0.0f;

    const float* Aptr = A + (size_t)(bm + lr) * K + lc;
    const float* Wptr = W + (size_t)(bn + lr) * K + lc;

    for (int k0 = 0; k0 < K; k0 += 16) {
        float4 av = *(const float4*)(Aptr + k0);
        As[lc + 0][lr] = av.x; As[lc + 1][lr] = av.y;
        As[lc + 2][lr] = av.z; As[lc + 3][lr] = av.w;
#pragma unroll
        for (int i = 0; i < 4; i++) {
            float4 wv = *(const float4*)(Wptr + (size_t)i * 32 * K + k0);
            int nr = lr + i * 32;
            Bs[lc + 0][nr] = wv.x; Bs[lc + 1][nr] = wv.y;
            Bs[lc + 2][nr] = wv.z; Bs[lc + 3][nr] = wv.w;
        }
        __syncthreads();
#pragma unroll
        for (int k = 0; k < 16; k++) {
            float a[4], b[8];
            *(float4*)a       = *(const float4*)&As[k][tr * 4];
            *(float4*)b       = *(const float4*)&Bs[k][tc * 8];
            *(float4*)(b + 4) = *(const float4*)&Bs[k][tc * 8 + 4];
#pragma unroll
            for (int i = 0; i < 4; i++)
#pragma unroll
                for (int j = 0; j < 8; j++)
                    acc[i][j] += a[i] * b[j];
        }
        __syncthreads();
    }

#pragma unroll
    for (int i = 0; i < 4; i++) {
        int r = bm + tr * 4 + i;
#pragma unroll
        for (int j = 0; j < 8; j++) {
            int c = bn + tc * 8 + j;
            Cout[(size_t)r * N + c] = acc[i][j] + bias[c];
        }
    }
}

// ---------------- helpers for the tensor-core kernel -------------------------
__device__ __forceinline__ uint32_t smem_u32(const void* p) {
    return (uint32_t)__cvta_generic_to_shared(p);
}
__device__ __forceinline__ void cp16(uint32_t dst, const void* src) {
    asm volatile("cp.async.ca.shared.global [%0], [%1], 16;" :: "r"(dst), "l"(src));
}
__device__ __forceinline__ void cp_commit() {
    asm volatile("cp.async.commit_group;");
}
template<int N> __device__ __forceinline__ void cp_wait() {
    asm volatile("cp.async.wait_group %0;" :: "n"(N));
}
__device__ __forceinline__ void ldm_x4(uint32_t* r, uint32_t addr) {
    asm volatile("ldmatrix.sync.aligned.m8n8.x4.shared.b16 {%0,%1,%2,%3}, [%4];"
                 : "=r"(r[0]), "=r"(r[1]), "=r"(r[2]), "=r"(r[3]) : "r"(addr));
}
__device__ __forceinline__ void mma16816(float* c, const uint32_t* a,
                                          uint32_t b0, uint32_t b1) {
    asm volatile(
        "mma.sync.aligned.m16n8k16.row.col.f32.bf16.bf16.f32 "
        "{%0,%1,%2,%3}, {%4,%5,%6,%7}, {%8,%9}, {%0,%1,%2,%3};"
        : "+f"(c[0]), "+f"(c[1]), "+f"(c[2]), "+f"(c[3])
        : "r"(a[0]), "r"(a[1]), "r"(a[2]), "r"(a[3]), "r"(b0), "r"(b1));
}

// ---------------- bf16 MMA GEMM: C = A@(B0+B1+B2)^T + bias -------------------
// A [M,K] bf16 (exact spikes), Bp [N,K] bf16 (exact 3-split weights).
// Twin accumulators: B0-pass -> acc_h;  B1,B2 passes -> acc_ml; C = h + ml + bias.
// BM=64, BN=128, BK=32; 256 threads = 8 warps (2M x 4N); cp.async double buffer.
#define MMA_BM 64
#define MMA_MI 2          // 16-row tiles per warp (WM=32)
#define A_STG (MMA_BM*40*2)     // 5120 B per stage
#define B_STG (128*40*2)        // 10240 B per stage

__global__ void __launch_bounds__(256)
mma3_gemm(const bf16* __restrict__ A,
          const bf16* __restrict__ B0, const bf16* __restrict__ B1,
          const bf16* __restrict__ B2,
          const float* __restrict__ bias, float* __restrict__ C,
          int K, int N)
{
    __shared__ bf16 As[2][MMA_BM][40];
    __shared__ bf16 Bs[2][128][40];

    const int tid  = threadIdx.x;
    const int lane = tid & 31;
    const int wid  = tid >> 5;
    const int wm   = wid >> 2;      // 0..1
    const int wn   = wid & 3;       // 0..3
    const int g    = lane >> 2;
    const int q    = lane & 3;
    const int bm   = blockIdx.x * MMA_BM;
    const int bn   = blockIdx.y * 128;

    const uint32_t As_base = smem_u32(&As[0][0][0]);
    const uint32_t Bs_base = smem_u32(&Bs[0][0][0]);

    // ldmatrix per-lane byte offsets (within a stage)
    uint32_t a_off[MMA_MI];
#pragma unroll
    for (int i = 0; i < MMA_MI; i++)
        a_off[i] = ((wm * 32 + i * 16 + (lane & 15)) * 40 + ((lane >> 4) & 1) * 8) * 2;
    uint32_t b_off[2];
#pragma unroll
    for (int jj = 0; jj < 2; jj++)
        b_off[jj] = ((wn * 32 + jj * 16 + ((lane >> 4) & 1) * 8 + (lane & 7)) * 40
                     + ((lane >> 3) & 1) * 8) * 2;

    // cp.async source coords
    const int arow = tid >> 2, ac8 = (tid & 3) * 8;           // A: 1 chunk/thread

    float acc_h[MMA_MI][4][4], acc_ml[MMA_MI][4][4];
#pragma unroll
    for (int i = 0; i < MMA_MI; i++)
#pragma unroll
        for (int j = 0; j < 4; j++)
#pragma unroll
            for (int r = 0; r < 4; r++) { acc_h[i][j][r] = 0.0f; acc_ml[i][j][r] = 0.0f; }

    const int ktiles = K / 32;
    const int ktot   = ktiles * 3;

    // issue tile `tn` into stage `st`
    auto issue = [&](int tn, int st) {
        int p  = tn / ktiles;
        int kc = (tn - p * ktiles) * 32;
        const bf16* Bp = (p == 0) ? B0 : ((p == 1) ? B1 : B2);
        cp16(As_base + st * A_STG + (arow * 40 + ac8) * 2,
             A + (size_t)(bm + arow) * K + kc + ac8);
#pragma unroll
        for (int r = 0; r < 2; r++) {
            int u = tid + r * 256, row = u >> 2, c8 = (u & 3) * 8;
            cp16(Bs_base + st * B_STG + (row * 40 + c8) * 2,
                 Bp + (size_t)(bn + row) * K + kc + c8);
        }
        cp_commit();
    };

    issue(0, 0);

    for (int kt = 0; kt < ktot; kt++) {
        const int st = kt & 1;
        if (kt + 1 < ktot) { issue(kt + 1, (kt + 1) & 1); cp_wait<1>(); }
        else               { cp_wait<0>(); }
        __syncthreads();

        const bool is_h = (kt < ktiles);
#pragma unroll
        for (int kk = 0; kk < 32; kk += 16) {
            uint32_t af[MMA_MI][4], bf[2][4];
#pragma unroll
            for (int i = 0; i < MMA_MI; i++)
                ldm_x4(af[i], As_base + st * A_STG + a_off[i] + kk * 2);
#pragma unroll
            for (int jj = 0; jj < 2; jj++)
                ldm_x4(bf[jj], Bs_base + st * B_STG + b_off[jj] + kk * 2);

            if (is_h) {
#pragma unroll
                for (int i = 0; i < MMA_MI; i++)
#pragma unroll
                    for (int j = 0; j < 4; j++)
                        mma16816(acc_h[i][j], af[i], bf[j >> 1][(j & 1) * 2],
                                 bf[j >> 1][(j & 1) * 2 + 1]);
            } else {
#pragma unroll
                for (int i = 0; i < MMA_MI; i++)
#pragma unroll
                    for (int j = 0; j < 4; j++)
                        mma16816(acc_ml[i][j], af[i], bf[j >> 1][(j & 1) * 2],
                                 bf[j >> 1][(j & 1) * 2 + 1]);
            }
        }
        __syncthreads();
    }

    // epilogue: C = acc_h + acc_ml + bias
#pragma unroll
    for (int i = 0; i < MMA_MI; i++) {
        int r0 = bm + wm * 32 + i * 16 + g;
#pragma unroll
        for (int j = 0; j < 4; j++) {
            int c0 = bn + wn * 32 + j * 8 + q * 2;
            float bv0 = bias[c0], bv1 = bias[c0 + 1];
            C[(size_t)r0 * N + c0]           = acc_h[i][j][0] + acc_ml[i][j][0] + bv0;
            C[(size_t)r0 * N + c0 + 1]       = acc_h[i][j][1] + acc_ml[i][j][1] + bv1;
            C[(size_t)(r0 + 8) * N + c0]     = acc_h[i][j][2] + acc_ml[i][j][2] + bv0;
            C[(size_t)(r0 + 8) * N + c0 + 1] = acc_h[i][j][3] + acc_ml[i][j][3] + bv1;
        }
    }
}

// ---------------- LIF scans (time loop inside, states in registers) ----------
__global__ void lif1_scan_kernel()
{
    int idx = blockIdx.x * blockDim.x + threadIdx.x;   // b*NH + n
    if (idx >= BB * NH) return;
    float c = g_C1[idx];
    float m = 0.0f;
#pragma unroll
    for (int t = 0; t < TSTEPS; t++) {
        m = BETA * m + c;
        float s = (m - THRESH > 0.0f) ? 1.0f : 0.0f;
        m -= s * THRESH;
        g_spk1[(size_t)t * (BB * NH) + idx] = __float2bfloat16_rn(s);
    }
}

__global__ void lif2_scan_kernel()
{
    int idx = blockIdx.x * blockDim.x + threadIdx.x;   // b*NH + n
    if (idx >= BB * NH) return;
    float m = 0.0f;
#pragma unroll
    for (int t = 0; t < TSTEPS; t++) {
        float c = g_C2[(size_t)t * (BB * NH) + idx];
        m = BETA * m + c;
        float s = (m - THRESH > 0.0f) ? 1.0f : 0.0f;
        m -= s * THRESH;
        g_spk2[(size_t)t * (BB * NH) + idx] = __float2bfloat16_rn(s);
    }
}

__global__ void lif3_scan_kernel(float* __restrict__ out)
{
    int idx = blockIdx.x * blockDim.x + threadIdx.x;   // b*NC + c
    if (idx >= BB * NC) return;
    int b = idx / NC;
    int c = idx - b * NC;
    float m = 0.0f;
#pragma unroll
    for (int t = 0; t < TSTEPS; t++) {
        float cur = g_C3[(size_t)(t * BB + b) * NCP + c];
        m = BETA * m + cur;
        float s = (m - THRESH > 0.0f) ? 1.0f : 0.0f;
        m -= s * THRESH;
        out[(size_t)t * (BB * NC) + idx] = s;                               // spk_rec
        out[(size_t)TSTEPS * (BB * NC) + (size_t)t * (BB * NC) + idx] = m;  // mem_rec
    }
}

// ---------------- launch ------------------------------------------------------
extern "C" void kernel_launch(void* const* d_in, const int* in_sizes, int n_in,
                              void* d_out, int out_size)
{
    const float* x  = (const float*)d_in[0];
    const float* W1 = (const float*)d_in[1];
    const float* b1 = (const float*)d_in[2];
    const float* W2 = (const float*)d_in[3];
    const float* b2 = (const float*)d_in[4];
    const float* W3 = (const float*)d_in[5];
    const float* b3 = (const float*)d_in[6];
    float* out = (float*)d_out;

    bf16 *w2h, *w2m, *w2l, *w3h, *w3m, *w3l, *spk1, *spk2;
    float *C1, *C2, *C3, *b3p;
    cudaGetSymbolAddress((void**)&w2h, g_w2h); cudaGetSymbolAddress((void**)&w2m, g_w2m);
    cudaGetSymbolAddress((void**)&w2l, g_w2l);
    cudaGetSymbolAddress((void**)&w3h, g_w3h); cudaGetSymbolAddress((void**)&w3m, g_w3m);
    cudaGetSymbolAddress((void**)&w3l, g_w3l);
    cudaGetSymbolAddress((void**)&spk1, g_spk1);
    cudaGetSymbolAddress((void**)&spk2, g_spk2);
    cudaGetSymbolAddress((void**)&C1, g_C1);
    cudaGetSymbolAddress((void**)&C2, g_C2);
    cudaGetSymbolAddress((void**)&C3, g_C3);
    cudaGetSymbolAddress((void**)&b3p, g_b3p);

    // weight splits (exact 24-bit decompositions)
    conv3_kernel<<<(NH * NH + 255) / 256, 256>>>(W2, w2h, w2m, w2l, NH * NH);
    conv3_w3_kernel<<<(NCP * NH + 255) / 256, 256>>>(W3);
    b3pad_kernel<<<1, 128>>>(b3);

    // GEMM1 (fp32, proven): cur1 = x @ W1^T + b1  — loop-invariant, once
    gemm_f32_kernel<<<dim3(BB / 32, NH / 128), 128>>>(x, W1, b1, C1, NIN, NH);

    // LIF layer 1, all 25 steps
    lif1_scan_kernel<<<(BB * NH + 255) / 256, 256>>>();

    // GEMM2 (tensor cores): cur2_all = spk1_all @ W2^T + b2   (M = 6400)
    mma3_gemm<<<dim3(MT / MMA_BM, NH / 128), 256>>>(spk1, w2h, w2m, w2l, b2, C2, NH, NH);

    lif2_scan_kernel<<<(BB * NH + 255) / 256, 256>>>();

    // GEMM3 (tensor cores): cur3_all = spk2_all @ W3p^T + b3p (M = 6400, N = 128)
    mma3_gemm<<<dim3(MT / MMA_BM, NCP / 128), 256>>>(spk2, w3h, w3m, w3l, b3p, C3, NH, NCP);

    lif3_scan_kernel<<<(BB * NC + 255) / 256, 256>>>(out);
}